// round 14
// baseline (speedup 1.0000x reference)
#include <cuda_runtime.h>
#include <cuda_bf16.h>

#define NB 8
#define NI 64
#define NO 64
#define NN 8192
#define NK 16
#define ND 3
#define NH1 16
#define NH2 32
#define TN 8
#define ROWS 128
#define NTHREADS 256
#define BON (NB*NO*NN)
#define SPN (NB*ND*NN)
#define CSTRIDE (NN*NK)

typedef unsigned long long u64;
typedef unsigned int u32;

// ---- smem layout (floats) ----
#define XPAD 132
#define SM_X     0                        // X fp32 [c:64][row padded 132] = 33792 B
#define SM_SCR   33792                    // H scratch fp32 [row:128][42] = 21504 B
#define SM_SMALL (33792 + 21504)
#define SMEM_BYTES (SM_SMALL + 1248*4)    // 60288 B -> 3 CTAs/SM
#define SCR_PAD 42

// ---- global fragment buffers (built once per launch by prep kernel) ----
__device__ uint4 g_bf[32*32];
__device__ uint4 g_b2f[16*32];

__device__ __forceinline__ u64 pack2(float x, float y) {
    u64 r; asm("mov.b64 %0,{%1,%2};" : "=l"(r) : "f"(x), "f"(y)); return r;
}
__device__ __forceinline__ u64 fma2(u64 a, u64 b, u64 c) {
    u64 d; asm("fma.rn.f32x2 %0,%1,%2,%3;" : "=l"(d) : "l"(a), "l"(b), "l"(c)); return d;
}
__device__ __forceinline__ float2 unpack2(u64 v) {
    float2 f; asm("mov.b64 {%0,%1},%2;" : "=f"(f.x), "=f"(f.y) : "l"(v)); return f;
}
__device__ __forceinline__ u32 bf2bits(__nv_bfloat162 h) { return *reinterpret_cast<u32*>(&h); }

__device__ __forceinline__ void split_pair(float f0, float f1, u32& hi, u32& lo) {
    __nv_bfloat162 hb = __float22bfloat162_rn(make_float2(f0, f1));
    float2 hf = __bfloat1622float2(hb);
    __nv_bfloat162 lb = __float22bfloat162_rn(make_float2(f0 - hf.x, f1 - hf.y));
    hi = bf2bits(hb); lo = bf2bits(lb);
}

#define MMA16816(c, a, b) \
    asm volatile("mma.sync.aligned.m16n8k16.row.col.f32.bf16.bf16.f32 " \
        "{%0,%1,%2,%3}, {%4,%5,%6,%7}, {%8,%9}, {%0,%1,%2,%3};" \
        : "+f"((c)[0]), "+f"((c)[1]), "+f"((c)[2]), "+f"((c)[3]) \
        : "r"((a).x), "r"((a).y), "r"((a).z), "r"((a).w), \
          "r"((b).x), "r"((b).y))

// ================= prep kernel: build B fragments once =================
__global__ void pccn_prep(const float* __restrict__ weight, const float* __restrict__ W3)
{
    const int tid  = threadIdx.x;
    const int lane = tid & 31;
    const int gid  = lane >> 2;
    const int tig  = lane & 3;
    for (int blk = tid >> 5; blk < 32; blk += 8) {
        int nt = blk >> 2, s = blk & 3;
        int n = 8*nt + gid, k0 = 16*s + 2*tig;
        float w00 = weight[k0*NO + n],     w01 = weight[(k0+1)*NO + n];
        float w10 = weight[(k0+8)*NO + n], w11 = weight[(k0+9)*NO + n];
        u32 h0,l0,h1,l1;
        split_pair(w00, w01, h0, l0);
        split_pair(w10, w11, h1, l1);
        g_bf[blk*32 + lane] = make_uint4(h0, h1, l0, l1);
    }
    for (int blk = tid >> 5; blk < 16; blk += 8) {
        int nt = blk >> 1, s = blk & 1;
        int n = 8*nt + gid, k0 = 16*s + 2*tig;
        float w00 = W3[k0*NO + n],     w01 = W3[(k0+1)*NO + n];
        float w10 = W3[(k0+8)*NO + n], w11 = W3[(k0+9)*NO + n];
        u32 h0,l0,h1,l1;
        split_pair(w00, w01, h0, l0);
        split_pair(w10, w11, h1, l1);
        g_b2f[blk*32 + lane] = make_uint4(h0, h1, l0, l1);
    }
}

__global__ void __launch_bounds__(NTHREADS, 3)
pccn_kernel(const float* __restrict__ input, const float* __restrict__ points,
            const float* __restrict__ support, const float* __restrict__ bias,
            const float* __restrict__ W1, const float* __restrict__ b1,
            const float* __restrict__ W2, const float* __restrict__ b2,
            const float* __restrict__ b3, float* __restrict__ out, int copy_sp)
{
    extern __shared__ char smemc[];
    float* sX  = (float*)(smemc + SM_X);      // [c][XPAD]
    float* scr = (float*)(smemc + SM_SCR);    // [row][SCR_PAD]
    float* sW1   = (float*)(smemc + SM_SMALL);
    float* sb1   = sW1 + 48;
    float* sW2   = sb1 + 16;
    float* sb2   = sW2 + 512;
    float* sb3   = sb2 + 32;
    float* sBias = sb3 + 64;
    float* sOut  = sBias + 64;        // [n_local:8][o:64]

    const int tid  = threadIdx.x;
    const int warp = tid >> 5;
    const int lane = tid & 31;
    const int gid  = lane >> 2;
    const int tig  = lane & 3;
    const int blk  = blockIdx.x;
    const int b    = blk >> 10;
    const int n0   = (blk & 1023) * TN;

    // ---- small arrays ----
    for (int idx = tid; idx < NH1*NH2; idx += NTHREADS) sW2[idx] = W2[idx];
    if (tid < 48) sW1[tid]  = W1[tid];
    if (tid < 16) sb1[tid]  = b1[tid];
    if (tid < 32) sb2[tid]  = b2[tid];
    if (tid < 64) sb3[tid]  = b3[tid];
    if (tid < 64) sBias[tid] = bias[tid];

    // ========== stage X: coalesced LDG.128 -> conflict-free STS.128 ==========
    {
        const float* base = input + (size_t)b*NI*CSTRIDE + (size_t)n0*NK;
#pragma unroll
        for (int it = 0; it < 8; it++) {
            int idx = tid + it*NTHREADS;       // (i:64, q:32)
            int i = idx >> 5, q = idx & 31;
            float4 v = *(const float4*)(base + (size_t)i*CSTRIDE + 4*q);
            *(float4*)(sX + i*XPAD + 4*q) = v;
        }
    }

    __syncthreads();   // small arrays (MLP weights) ready — REQUIRED before MLP reads

    // ========== coords + MLP, all 256 threads (row = tid&127, half ph) ==========
    {
        const int row = tid & 127;
        const int ph  = tid >> 7;              // 0: j 0..15, 1: j 16..31
        const int k = row & 15;
        const int n = n0 + (row >> 4);
        float p0 = points[(((size_t)b*ND + 0)*NN + n)*NK + k] - support[((size_t)b*ND + 0)*NN + n];
        float p1 = points[(((size_t)b*ND + 1)*NN + n)*NK + k] - support[((size_t)b*ND + 1)*NN + n];
        float p2 = points[(((size_t)b*ND + 2)*NN + n)*NK + k] - support[((size_t)b*ND + 2)*NN + n];
        float sq = p0*p0 + p1*p1 + p2*p2;
        float m = sq;
#pragma unroll
        for (int off = 8; off > 0; off >>= 1)
            m = fmaxf(m, __shfl_xor_sync(0xffffffffu, m, off));
        float maxi = sqrtf(m);
        maxi += (maxi == 0.0f) ? 1.0f : 0.0f;
        float inv = 1.0f / maxi;
        float x0 = p0*inv, x1 = p1*inv, x2 = p2*inv;

        float h1[NH1];
#pragma unroll
        for (int a = 0; a < NH1; a++) {
            float v = sb1[a] + x0*sW1[a] + x1*sW1[16 + a] + x2*sW1[32 + a];
            h1[a] = fmaxf(v, 0.0f);
        }
        u64 h2p[8];
        const u64* sb2p = (const u64*)(sb2 + 16*ph);
#pragma unroll
        for (int jj = 0; jj < 8; jj++) h2p[jj] = sb2p[jj];
#pragma unroll
        for (int a = 0; a < NH1; a++) {
            u64 xd = pack2(h1[a], h1[a]);
            const u64* wrow = (const u64*)(sW2 + a*NH2 + 16*ph);
#pragma unroll
            for (int jj = 0; jj < 8; jj++) h2p[jj] = fma2(xd, wrow[jj], h2p[jj]);
        }
#pragma unroll
        for (int jj = 0; jj < 8; jj++) {
            float2 v = unpack2(h2p[jj]);
            v.x = fmaxf(v.x, 0.0f); v.y = fmaxf(v.y, 0.0f);
            *(float2*)(scr + row*SCR_PAD + 16*ph + 2*jj) = v;
        }
    }

    __syncthreads();

    // ========== GEMMs via mma.sync (warp w -> rows 16w..16w+15 = n_local w) ==========
    float c1[8][4], c2[8][4];
#pragma unroll
    for (int nt = 0; nt < 8; nt++)
#pragma unroll
        for (int r = 0; r < 4; r++) { c1[nt][r] = 0.0f; c2[nt][r] = 0.0f; }

    const int r0 = 16*warp + gid;

    // GEMM1: C1 = X @ W (K=64), A from smem (conflict-free LDS.32), B from global L1
#pragma unroll
    for (int s = 0; s < 4; s++) {
        const int c0 = 16*s + 2*tig;
        uint4 ah, al;
        split_pair(sX[c0*XPAD + r0],           sX[(c0+1)*XPAD + r0],           ah.x, al.x);
        split_pair(sX[c0*XPAD + r0 + 8],       sX[(c0+1)*XPAD + r0 + 8],       ah.y, al.y);
        split_pair(sX[(c0+8)*XPAD + r0],       sX[(c0+9)*XPAD + r0],           ah.z, al.z);
        split_pair(sX[(c0+8)*XPAD + r0 + 8],   sX[(c0+9)*XPAD + r0 + 8],       ah.w, al.w);
#pragma unroll
        for (int nt = 0; nt < 8; nt++) {
            uint4 bb = __ldg(&g_bf[(nt*4 + s)*32 + lane]);
            uint2 bh = make_uint2(bb.x, bb.y);
            uint2 bl = make_uint2(bb.z, bb.w);
            MMA16816(c1[nt], ah, bh);
            MMA16816(c1[nt], ah, bl);
            MMA16816(c1[nt], al, bh);
        }
    }
    // GEMM2: C2 = H @ W3 (K=32), A from scratch
#pragma unroll
    for (int s = 0; s < 2; s++) {
        const int c0 = 16*s + 2*tig;
        float2 p00 = *(const float2*)(scr + r0*SCR_PAD + c0);
        float2 p10 = *(const float2*)(scr + (r0+8)*SCR_PAD + c0);
        float2 p01 = *(const float2*)(scr + r0*SCR_PAD + c0 + 8);
        float2 p11 = *(const float2*)(scr + (r0+8)*SCR_PAD + c0 + 8);
        uint4 ah, al;
        split_pair(p00.x, p00.y, ah.x, al.x);
        split_pair(p10.x, p10.y, ah.y, al.y);
        split_pair(p01.x, p01.y, ah.z, al.z);
        split_pair(p11.x, p11.y, ah.w, al.w);
#pragma unroll
        for (int nt = 0; nt < 8; nt++) {
            uint4 bb = __ldg(&g_b2f[(nt*2 + s)*32 + lane]);
            uint2 bh = make_uint2(bb.x, bb.y);
            uint2 bl = make_uint2(bb.z, bb.w);
            MMA16816(c2[nt], ah, bh);
            MMA16816(c2[nt], ah, bl);
            MMA16816(c2[nt], al, bh);
        }
    }

    // ========== combine: out[n,o] = sum_rows C1 * (C2 + b3) ==========
    {
#pragma unroll
        for (int nt = 0; nt < 8; nt++) {
            float b3e = sb3[8*nt + 2*tig];
            float b3o = sb3[8*nt + 2*tig + 1];
            float s0 = c1[nt][0]*(c2[nt][0] + b3e) + c1[nt][2]*(c2[nt][2] + b3e);
            float s1 = c1[nt][1]*(c2[nt][1] + b3o) + c1[nt][3]*(c2[nt][3] + b3o);
#pragma unroll
            for (int msk = 4; msk <= 16; msk <<= 1) {
                s0 += __shfl_xor_sync(0xffffffffu, s0, msk);
                s1 += __shfl_xor_sync(0xffffffffu, s1, msk);
            }
            if (lane < 4) {
                sOut[warp*NO + 8*nt + 2*tig]     = s0;
                sOut[warp*NO + 8*nt + 2*tig + 1] = s1;
            }
        }
    }

    __syncthreads();

    // ========== epilogue: out (B, O, N) + bias ==========
    if (tid < 128) {
        int o = tid >> 1, half = tid & 1;
        float4 rr;
        rr.x = sOut[(half*4+0)*NO + o] + sBias[o];
        rr.y = sOut[(half*4+1)*NO + o] + sBias[o];
        rr.z = sOut[(half*4+2)*NO + o] + sBias[o];
        rr.w = sOut[(half*4+3)*NO + o] + sBias[o];
        *(float4*)(out + ((size_t)b*NO + o)*NN + n0 + half*4) = rr;
    }

    // ---- support_points passthrough ----
    if (copy_sp) {
        for (int idx = blk*NTHREADS + tid; idx < SPN; idx += gridDim.x*NTHREADS)
            out[BON + idx] = support[idx];
    }
}

extern "C" void kernel_launch(void* const* d_in, const int* in_sizes, int n_in,
                              void* d_out, int out_size) {
    const float* input   = (const float*)d_in[0];
    const float* points  = (const float*)d_in[1];
    const float* support = (const float*)d_in[2];
    const float* weight  = (const float*)d_in[3];
    const float* bias    = (const float*)d_in[4];
    const float* W1      = (const float*)d_in[5];
    const float* b1      = (const float*)d_in[6];
    const float* W2      = (const float*)d_in[7];
    const float* b2      = (const float*)d_in[8];
    const float* W3      = (const float*)d_in[9];
    const float* b3      = (const float*)d_in[10];

    static int inited = 0;
    if (!inited) {
        cudaFuncSetAttribute(pccn_kernel,
                             cudaFuncAttributeMaxDynamicSharedMemorySize,
                             SMEM_BYTES);
        inited = 1;
    }
    int copy_sp = (out_size > BON) ? 1 : 0;
    pccn_prep<<<1, NTHREADS>>>(weight, W3);
    pccn_kernel<<<NB*(NN/TN), NTHREADS, SMEM_BYTES>>>(
        input, points, support, bias, W1, b1, W2, b2, b3,
        (float*)d_out, copy_sp);
}

// round 15
// speedup vs baseline: 1.2315x; 1.2315x over previous
#include <cuda_runtime.h>
#include <cuda_bf16.h>

#define NB 8
#define NI 64
#define NO 64
#define NN 8192
#define NK 16
#define ND 3
#define NH1 16
#define NH2 32
#define TN 8
#define ROWS 128
#define NTHREADS 256
#define BON (NB*NO*NN)
#define SPN (NB*ND*NN)
#define CSTRIDE (NN*NK)

typedef unsigned long long u64;
typedef unsigned int u32;

// ---- smem layout (bytes) ----
// X planes: u32 [cp:32][136]  (bf16x2 hi / lo of channel pairs)  17408 B each
// H planes: u32 [jp:16][136]                                      8704 B each
#define PPAD 136
#define SM_XH    0
#define SM_XL    17408
#define SM_SH    34816
#define SM_SL    43520
#define SM_SMALL 52224
#define SMEM_BYTES (SM_SMALL + 1248*4)   // 57216 B -> 3 CTAs/SM

// ---- global fragment buffers (built once per launch by prep kernel) ----
__device__ uint4 g_bf[32*32];
__device__ uint4 g_b2f[16*32];

__device__ __forceinline__ u64 pack2(float x, float y) {
    u64 r; asm("mov.b64 %0,{%1,%2};" : "=l"(r) : "f"(x), "f"(y)); return r;
}
__device__ __forceinline__ u64 fma2(u64 a, u64 b, u64 c) {
    u64 d; asm("fma.rn.f32x2 %0,%1,%2,%3;" : "=l"(d) : "l"(a), "l"(b), "l"(c)); return d;
}
__device__ __forceinline__ float2 unpack2(u64 v) {
    float2 f; asm("mov.b64 {%0,%1},%2;" : "=f"(f.x), "=f"(f.y) : "l"(v)); return f;
}
__device__ __forceinline__ u32 bf2bits(__nv_bfloat162 h) { return *reinterpret_cast<u32*>(&h); }

__device__ __forceinline__ void split_pair(float f0, float f1, u32& hi, u32& lo) {
    __nv_bfloat162 hb = __float22bfloat162_rn(make_float2(f0, f1));
    float2 hf = __bfloat1622float2(hb);
    __nv_bfloat162 lb = __float22bfloat162_rn(make_float2(f0 - hf.x, f1 - hf.y));
    hi = bf2bits(hb); lo = bf2bits(lb);
}

#define MMA16816(c, a, b) \
    asm volatile("mma.sync.aligned.m16n8k16.row.col.f32.bf16.bf16.f32 " \
        "{%0,%1,%2,%3}, {%4,%5,%6,%7}, {%8,%9}, {%0,%1,%2,%3};" \
        : "+f"((c)[0]), "+f"((c)[1]), "+f"((c)[2]), "+f"((c)[3]) \
        : "r"((a).x), "r"((a).y), "r"((a).z), "r"((a).w), \
          "r"((b).x), "r"((b).y))

// ================= prep kernel: build B fragments once =================
__global__ void pccn_prep(const float* __restrict__ weight, const float* __restrict__ W3)
{
    const int tid  = threadIdx.x;
    const int lane = tid & 31;
    const int gid  = lane >> 2;
    const int tig  = lane & 3;
    for (int blk = tid >> 5; blk < 32; blk += 8) {
        int nt = blk >> 2, s = blk & 3;
        int n = 8*nt + gid, k0 = 16*s + 2*tig;
        float w00 = weight[k0*NO + n],     w01 = weight[(k0+1)*NO + n];
        float w10 = weight[(k0+8)*NO + n], w11 = weight[(k0+9)*NO + n];
        u32 h0,l0,h1,l1;
        split_pair(w00, w01, h0, l0);
        split_pair(w10, w11, h1, l1);
        g_bf[blk*32 + lane] = make_uint4(h0, h1, l0, l1);
    }
    for (int blk = tid >> 5; blk < 16; blk += 8) {
        int nt = blk >> 1, s = blk & 1;
        int n = 8*nt + gid, k0 = 16*s + 2*tig;
        float w00 = W3[k0*NO + n],     w01 = W3[(k0+1)*NO + n];
        float w10 = W3[(k0+8)*NO + n], w11 = W3[(k0+9)*NO + n];
        u32 h0,l0,h1,l1;
        split_pair(w00, w01, h0, l0);
        split_pair(w10, w11, h1, l1);
        g_b2f[blk*32 + lane] = make_uint4(h0, h1, l0, l1);
    }
}

__global__ void __launch_bounds__(NTHREADS, 3)
pccn_kernel(const float* __restrict__ input, const float* __restrict__ points,
            const float* __restrict__ support, const float* __restrict__ bias,
            const float* __restrict__ W1, const float* __restrict__ b1,
            const float* __restrict__ W2, const float* __restrict__ b2,
            const float* __restrict__ b3, float* __restrict__ out, int copy_sp)
{
    extern __shared__ char smemc[];
    u32* sXh = (u32*)(smemc + SM_XH);   // [cp][PPAD]
    u32* sXl = (u32*)(smemc + SM_XL);
    u32* sHh = (u32*)(smemc + SM_SH);   // [jp][PPAD]
    u32* sHl = (u32*)(smemc + SM_SL);
    float* sW1   = (float*)(smemc + SM_SMALL);
    float* sb1   = sW1 + 48;
    float* sW2   = sb1 + 16;
    float* sb2   = sW2 + 512;
    float* sb3   = sb2 + 32;
    float* sBias = sb3 + 64;
    float* sOut  = sBias + 64;        // [n_local:8][o:64]

    const int tid  = threadIdx.x;
    const int warp = tid >> 5;
    const int lane = tid & 31;
    const int gid  = lane >> 2;
    const int tig  = lane & 3;
    const int ng   = warp & 3;        // rows 32ng..32ng+31 (n_local 2ng, 2ng+1)
    const int ch   = warp >> 2;       // nt in 4ch..4ch+3
    const int blk  = blockIdx.x;
    const int b    = blk >> 10;
    const int n0   = (blk & 1023) * TN;

    // ---- small arrays ----
    for (int idx = tid; idx < NH1*NH2; idx += NTHREADS) sW2[idx] = W2[idx];
    if (tid < 48) sW1[tid]  = W1[tid];
    if (tid < 16) sb1[tid]  = b1[tid];
    if (tid < 32) sb2[tid]  = b2[tid];
    if (tid < 64) sb3[tid]  = b3[tid];
    if (tid < 64) sBias[tid] = bias[tid];

    // ========== stage X: coalesced LDG.128 pairs -> bf16 hi/lo planes ==========
    {
        const float* base = input + (size_t)b*NI*CSTRIDE + (size_t)n0*NK;
#pragma unroll
        for (int it = 0; it < 4; it++) {
            int idx = tid + it*NTHREADS;       // (cp:32, rq:32)
            int cp = idx >> 5, rq = idx & 31;
            float4 v0 = *(const float4*)(base + (size_t)(2*cp)*CSTRIDE + 4*rq);
            float4 v1 = *(const float4*)(base + (size_t)(2*cp+1)*CSTRIDE + 4*rq);
            uint4 h, l;
            split_pair(v0.x, v1.x, h.x, l.x);
            split_pair(v0.y, v1.y, h.y, l.y);
            split_pair(v0.z, v1.z, h.z, l.z);
            split_pair(v0.w, v1.w, h.w, l.w);
            *(uint4*)(sXh + cp*PPAD + 4*rq) = h;
            *(uint4*)(sXl + cp*PPAD + 4*rq) = l;
        }
    }

    __syncthreads();   // MLP weights ready before MLP reads them

    // ========== coords + MLP, all 256 threads (row = tid&127, half ph) ==========
    {
        const int row = tid & 127;
        const int ph  = tid >> 7;              // 0: j 0..15, 1: j 16..31
        const int k = row & 15;
        const int n = n0 + (row >> 4);
        float p0 = points[(((size_t)b*ND + 0)*NN + n)*NK + k] - support[((size_t)b*ND + 0)*NN + n];
        float p1 = points[(((size_t)b*ND + 1)*NN + n)*NK + k] - support[((size_t)b*ND + 1)*NN + n];
        float p2 = points[(((size_t)b*ND + 2)*NN + n)*NK + k] - support[((size_t)b*ND + 2)*NN + n];
        float sq = p0*p0 + p1*p1 + p2*p2;
        float m = sq;
#pragma unroll
        for (int off = 8; off > 0; off >>= 1)
            m = fmaxf(m, __shfl_xor_sync(0xffffffffu, m, off));
        float maxi = sqrtf(m);
        maxi += (maxi == 0.0f) ? 1.0f : 0.0f;
        float inv = 1.0f / maxi;
        float x0 = p0*inv, x1 = p1*inv, x2 = p2*inv;

        float h1[NH1];
#pragma unroll
        for (int a = 0; a < NH1; a++) {
            float v = sb1[a] + x0*sW1[a] + x1*sW1[16 + a] + x2*sW1[32 + a];
            h1[a] = fmaxf(v, 0.0f);
        }
        u64 h2p[8];
        const u64* sb2p = (const u64*)(sb2 + 16*ph);
#pragma unroll
        for (int jj = 0; jj < 8; jj++) h2p[jj] = sb2p[jj];
#pragma unroll
        for (int a = 0; a < NH1; a++) {
            u64 xd = pack2(h1[a], h1[a]);
            const u64* wrow = (const u64*)(sW2 + a*NH2 + 16*ph);
#pragma unroll
            for (int jj = 0; jj < 8; jj++) h2p[jj] = fma2(xd, wrow[jj], h2p[jj]);
        }
#pragma unroll
        for (int jj = 0; jj < 8; jj++) {
            float2 v = unpack2(h2p[jj]);
            v.x = fmaxf(v.x, 0.0f); v.y = fmaxf(v.y, 0.0f);
            u32 hi, lo; split_pair(v.x, v.y, hi, lo);
            int jp = 8*ph + jj;                // pair (j=2jp, 2jp+1)
            sHh[jp*PPAD + row] = hi;
            sHl[jp*PPAD + row] = lo;
        }
    }

    __syncthreads();

    // ========== GEMMs: warp = (ng, ch): 2 m-tiles x 4 nt ==========
    float c1[2][4][4], c2[2][4][4];
#pragma unroll
    for (int m = 0; m < 2; m++)
#pragma unroll
        for (int nl = 0; nl < 4; nl++)
#pragma unroll
            for (int r = 0; r < 4; r++) { c1[m][nl][r] = 0.0f; c2[m][nl][r] = 0.0f; }

    const int rbase = 32*ng + gid;     // m-tile m adds 16m

    // GEMM1: C1 = X @ W (K=64)
#pragma unroll
    for (int s = 0; s < 4; s++) {
        const int kp = 8*s + tig;
        uint4 ah[2], al[2];
#pragma unroll
        for (int m = 0; m < 2; m++) {
            const int r = rbase + 16*m;
            ah[m].x = sXh[kp*PPAD + r];       al[m].x = sXl[kp*PPAD + r];
            ah[m].y = sXh[kp*PPAD + r + 8];   al[m].y = sXl[kp*PPAD + r + 8];
            ah[m].z = sXh[(kp+4)*PPAD + r];   al[m].z = sXl[(kp+4)*PPAD + r];
            ah[m].w = sXh[(kp+4)*PPAD + r + 8]; al[m].w = sXl[(kp+4)*PPAD + r + 8];
        }
#pragma unroll
        for (int nl = 0; nl < 4; nl++) {
            uint4 bb = __ldg(&g_bf[((4*ch + nl)*4 + s)*32 + lane]);
            uint2 bh = make_uint2(bb.x, bb.y);
            uint2 bl = make_uint2(bb.z, bb.w);
#pragma unroll
            for (int m = 0; m < 2; m++) {
                MMA16816(c1[m][nl], ah[m], bh);
                MMA16816(c1[m][nl], ah[m], bl);
                MMA16816(c1[m][nl], al[m], bh);
            }
        }
    }
    // GEMM2: C2 = H @ W3 (K=32)
#pragma unroll
    for (int s = 0; s < 2; s++) {
        const int kp = 8*s + tig;
        uint4 ah[2], al[2];
#pragma unroll
        for (int m = 0; m < 2; m++) {
            const int r = rbase + 16*m;
            ah[m].x = sHh[kp*PPAD + r];       al[m].x = sHl[kp*PPAD + r];
            ah[m].y = sHh[kp*PPAD + r + 8];   al[m].y = sHl[kp*PPAD + r + 8];
            ah[m].z = sHh[(kp+4)*PPAD + r];   al[m].z = sHl[(kp+4)*PPAD + r];
            ah[m].w = sHh[(kp+4)*PPAD + r + 8]; al[m].w = sHl[(kp+4)*PPAD + r + 8];
        }
#pragma unroll
        for (int nl = 0; nl < 4; nl++) {
            uint4 bb = __ldg(&g_b2f[((4*ch + nl)*2 + s)*32 + lane]);
            uint2 bh = make_uint2(bb.x, bb.y);
            uint2 bl = make_uint2(bb.z, bb.w);
#pragma unroll
            for (int m = 0; m < 2; m++) {
                MMA16816(c2[m][nl], ah[m], bh);
                MMA16816(c2[m][nl], ah[m], bl);
                MMA16816(c2[m][nl], al[m], bh);
            }
        }
    }

    // ========== combine: out[n,o] = sum_rows C1 * (C2 + b3) ==========
    {
#pragma unroll
        for (int m = 0; m < 2; m++) {
            const int n_loc = 2*ng + m;
#pragma unroll
            for (int nl = 0; nl < 4; nl++) {
                const int nt = 4*ch + nl;
                float b3e = sb3[8*nt + 2*tig];
                float b3o = sb3[8*nt + 2*tig + 1];
                float s0 = c1[m][nl][0]*(c2[m][nl][0] + b3e) + c1[m][nl][2]*(c2[m][nl][2] + b3e);
                float s1 = c1[m][nl][1]*(c2[m][nl][1] + b3o) + c1[m][nl][3]*(c2[m][nl][3] + b3o);
#pragma unroll
                for (int msk = 4; msk <= 16; msk <<= 1) {
                    s0 += __shfl_xor_sync(0xffffffffu, s0, msk);
                    s1 += __shfl_xor_sync(0xffffffffu, s1, msk);
                }
                if (lane < 4) {
                    sOut[n_loc*NO + 8*nt + 2*tig]     = s0;
                    sOut[n_loc*NO + 8*nt + 2*tig + 1] = s1;
                }
            }
        }
    }

    __syncthreads();

    // ========== epilogue: out (B, O, N) + bias ==========
    if (tid < 128) {
        int o = tid >> 1, half = tid & 1;
        float4 rr;
        rr.x = sOut[(half*4+0)*NO + o] + sBias[o];
        rr.y = sOut[(half*4+1)*NO + o] + sBias[o];
        rr.z = sOut[(half*4+2)*NO + o] + sBias[o];
        rr.w = sOut[(half*4+3)*NO + o] + sBias[o];
        *(float4*)(out + ((size_t)b*NO + o)*NN + n0 + half*4) = rr;
    }

    // ---- support_points passthrough ----
    if (copy_sp) {
        for (int idx = blk*NTHREADS + tid; idx < SPN; idx += gridDim.x*NTHREADS)
            out[BON + idx] = support[idx];
    }
}

extern "C" void kernel_launch(void* const* d_in, const int* in_sizes, int n_in,
                              void* d_out, int out_size) {
    const float* input   = (const float*)d_in[0];
    const float* points  = (const float*)d_in[1];
    const float* support = (const float*)d_in[2];
    const float* weight  = (const float*)d_in[3];
    const float* bias    = (const float*)d_in[4];
    const float* W1      = (const float*)d_in[5];
    const float* b1      = (const float*)d_in[6];
    const float* W2      = (const float*)d_in[7];
    const float* b2      = (const float*)d_in[8];
    const float* W3      = (const float*)d_in[9];
    const float* b3      = (const float*)d_in[10];

    static int inited = 0;
    if (!inited) {
        cudaFuncSetAttribute(pccn_kernel,
                             cudaFuncAttributeMaxDynamicSharedMemorySize,
                             SMEM_BYTES);
        inited = 1;
    }
    int copy_sp = (out_size > BON) ? 1 : 0;
    pccn_prep<<<1, NTHREADS>>>(weight, W3);
    pccn_kernel<<<NB*(NN/TN), NTHREADS, SMEM_BYTES>>>(
        input, points, support, bias, W1, b1, W2, b2, b3,
        (float*)d_out, copy_sp);
}

// round 16
// speedup vs baseline: 1.2454x; 1.0113x over previous
#include <cuda_runtime.h>
#include <cuda_bf16.h>

#define NB 8
#define NI 64
#define NO 64
#define NN 8192
#define NK 16
#define ND 3
#define NH1 16
#define NH2 32
#define TN 8
#define ROWS 128
#define NTHREADS 256
#define BON (NB*NO*NN)
#define SPN (NB*ND*NN)
#define CSTRIDE (NN*NK)

typedef unsigned long long u64;
typedef unsigned int u32;

// ---- smem layout (bytes) ----
// X tf32 plane: u32 [c:64][136]  = 34816 B
// H planes: u32 [jp:16][136] hi/lo = 8704 B each
#define XPAD 136
#define PPAD 136
#define SM_XT    0
#define SM_SH    34816
#define SM_SL    43520
#define SM_SMALL 52224
#define SMEM_BYTES (SM_SMALL + 1248*4)   // 57216 B -> 3 CTAs/SM

// ---- global fragment buffers (built once per launch by prep kernel) ----
// g_bt[(nt*4+cp)*32+lane] = tf32 B frags for chunks 2cp,2cp+1 (GEMM1)
// g_b2f[(nt*2+s)*32+lane] = bf16 hi/lo B frags (GEMM2)
__device__ uint4 g_bt[8*4*32];
__device__ uint4 g_b2f[16*32];

__device__ __forceinline__ u64 pack2(float x, float y) {
    u64 r; asm("mov.b64 %0,{%1,%2};" : "=l"(r) : "f"(x), "f"(y)); return r;
}
__device__ __forceinline__ u64 fma2(u64 a, u64 b, u64 c) {
    u64 d; asm("fma.rn.f32x2 %0,%1,%2,%3;" : "=l"(d) : "l"(a), "l"(b), "l"(c)); return d;
}
__device__ __forceinline__ float2 unpack2(u64 v) {
    float2 f; asm("mov.b64 {%0,%1},%2;" : "=f"(f.x), "=f"(f.y) : "l"(v)); return f;
}
__device__ __forceinline__ u32 bf2bits(__nv_bfloat162 h) { return *reinterpret_cast<u32*>(&h); }
__device__ __forceinline__ u32 f2tf32(float f) {
    u32 r; asm("cvt.rna.tf32.f32 %0,%1;" : "=r"(r) : "f"(f)); return r;
}

__device__ __forceinline__ void split_pair(float f0, float f1, u32& hi, u32& lo) {
    __nv_bfloat162 hb = __float22bfloat162_rn(make_float2(f0, f1));
    float2 hf = __bfloat1622float2(hb);
    __nv_bfloat162 lb = __float22bfloat162_rn(make_float2(f0 - hf.x, f1 - hf.y));
    hi = bf2bits(hb); lo = bf2bits(lb);
}

#define MMA16816(c, a, b) \
    asm volatile("mma.sync.aligned.m16n8k16.row.col.f32.bf16.bf16.f32 " \
        "{%0,%1,%2,%3}, {%4,%5,%6,%7}, {%8,%9}, {%0,%1,%2,%3};" \
        : "+f"((c)[0]), "+f"((c)[1]), "+f"((c)[2]), "+f"((c)[3]) \
        : "r"((a).x), "r"((a).y), "r"((a).z), "r"((a).w), \
          "r"((b).x), "r"((b).y))

#define MMATF32(c, a, b0, b1) \
    asm volatile("mma.sync.aligned.m16n8k8.row.col.f32.tf32.tf32.f32 " \
        "{%0,%1,%2,%3}, {%4,%5,%6,%7}, {%8,%9}, {%0,%1,%2,%3};" \
        : "+f"((c)[0]), "+f"((c)[1]), "+f"((c)[2]), "+f"((c)[3]) \
        : "r"((a).x), "r"((a).y), "r"((a).z), "r"((a).w), \
          "r"(b0), "r"(b1))

// ================= prep kernel: build B fragments once =================
__global__ void pccn_prep(const float* __restrict__ weight, const float* __restrict__ W3)
{
    const int tid  = threadIdx.x;
    const int lane = tid & 31;
    const int gid  = lane >> 2;
    const int tig  = lane & 3;
    // GEMM1: tf32 B frags, chunk pairs. b0=(k=tig,n), b1=(k=tig+4,n) per k8 chunk.
    for (int blk = tid >> 5; blk < 32; blk += 8) {
        int nt = blk >> 2, cp = blk & 3;
        int n = 8*nt + gid;
        int k0 = 16*cp;           // chunk 2cp starts at 8*(2cp)
        u32 b00 = f2tf32(weight[(k0 + tig)*NO + n]);
        u32 b01 = f2tf32(weight[(k0 + tig + 4)*NO + n]);
        u32 b10 = f2tf32(weight[(k0 + 8 + tig)*NO + n]);
        u32 b11 = f2tf32(weight[(k0 + 8 + tig + 4)*NO + n]);
        g_bt[blk*32 + lane] = make_uint4(b00, b01, b10, b11);
    }
    // GEMM2: bf16 hi/lo frags (unchanged)
    for (int blk = tid >> 5; blk < 16; blk += 8) {
        int nt = blk >> 1, s = blk & 1;
        int n = 8*nt + gid, k0 = 16*s + 2*tig;
        float w00 = W3[k0*NO + n],     w01 = W3[(k0+1)*NO + n];
        float w10 = W3[(k0+8)*NO + n], w11 = W3[(k0+9)*NO + n];
        u32 h0,l0,h1,l1;
        split_pair(w00, w01, h0, l0);
        split_pair(w10, w11, h1, l1);
        g_b2f[blk*32 + lane] = make_uint4(h0, h1, l0, l1);
    }
}

__global__ void __launch_bounds__(NTHREADS, 3)
pccn_kernel(const float* __restrict__ input, const float* __restrict__ points,
            const float* __restrict__ support, const float* __restrict__ bias,
            const float* __restrict__ W1, const float* __restrict__ b1,
            const float* __restrict__ W2, const float* __restrict__ b2,
            const float* __restrict__ b3, float* __restrict__ out, int copy_sp)
{
    extern __shared__ char smemc[];
    u32* sXt = (u32*)(smemc + SM_XT);   // [c][XPAD] tf32 bits
    u32* sHh = (u32*)(smemc + SM_SH);   // [jp][PPAD]
    u32* sHl = (u32*)(smemc + SM_SL);
    float* sW1   = (float*)(smemc + SM_SMALL);
    float* sb1   = sW1 + 48;
    float* sW2   = sb1 + 16;
    float* sb2   = sW2 + 512;
    float* sb3   = sb2 + 32;
    float* sBias = sb3 + 64;
    float* sOut  = sBias + 64;        // [n_local:8][o:64]

    const int tid  = threadIdx.x;
    const int warp = tid >> 5;
    const int lane = tid & 31;
    const int gid  = lane >> 2;
    const int tig  = lane & 3;
    const int ng   = warp & 3;        // rows 32ng..32ng+31 (n_local 2ng, 2ng+1)
    const int ch   = warp >> 2;       // nt in 4ch..4ch+3
    const int blk  = blockIdx.x;
    const int b    = blk >> 10;
    const int n0   = (blk & 1023) * TN;

    // ---- small arrays ----
    for (int idx = tid; idx < NH1*NH2; idx += NTHREADS) sW2[idx] = W2[idx];
    if (tid < 48) sW1[tid]  = W1[tid];
    if (tid < 16) sb1[tid]  = b1[tid];
    if (tid < 32) sb2[tid]  = b2[tid];
    if (tid < 64) sb3[tid]  = b3[tid];
    if (tid < 64) sBias[tid] = bias[tid];

    // ========== stage X: coalesced LDG.128 -> tf32 cvt -> conflict-free STS.128 ==========
    {
        const float* base = input + (size_t)b*NI*CSTRIDE + (size_t)n0*NK;
#pragma unroll
        for (int it = 0; it < 8; it++) {
            int idx = tid + it*NTHREADS;       // (i:64, rq:32)
            int i = idx >> 5, rq = idx & 31;
            float4 v = *(const float4*)(base + (size_t)i*CSTRIDE + 4*rq);
            uint4 t = make_uint4(f2tf32(v.x), f2tf32(v.y), f2tf32(v.z), f2tf32(v.w));
            *(uint4*)(sXt + i*XPAD + 4*rq) = t;
        }
    }

    __syncthreads();   // MLP weights ready before MLP reads them

    // ========== coords + MLP, all 256 threads (row = tid&127, half ph) ==========
    {
        const int row = tid & 127;
        const int ph  = tid >> 7;              // 0: j 0..15, 1: j 16..31
        const int k = row & 15;
        const int n = n0 + (row >> 4);
        float p0 = points[(((size_t)b*ND + 0)*NN + n)*NK + k] - support[((size_t)b*ND + 0)*NN + n];
        float p1 = points[(((size_t)b*ND + 1)*NN + n)*NK + k] - support[((size_t)b*ND + 1)*NN + n];
        float p2 = points[(((size_t)b*ND + 2)*NN + n)*NK + k] - support[((size_t)b*ND + 2)*NN + n];
        float sq = p0*p0 + p1*p1 + p2*p2;
        float m = sq;
#pragma unroll
        for (int off = 8; off > 0; off >>= 1)
            m = fmaxf(m, __shfl_xor_sync(0xffffffffu, m, off));
        float maxi = sqrtf(m);
        maxi += (maxi == 0.0f) ? 1.0f : 0.0f;
        float inv = 1.0f / maxi;
        float x0 = p0*inv, x1 = p1*inv, x2 = p2*inv;

        float h1[NH1];
#pragma unroll
        for (int a = 0; a < NH1; a++) {
            float v = sb1[a] + x0*sW1[a] + x1*sW1[16 + a] + x2*sW1[32 + a];
            h1[a] = fmaxf(v, 0.0f);
        }
        u64 h2p[8];
        const u64* sb2p = (const u64*)(sb2 + 16*ph);
#pragma unroll
        for (int jj = 0; jj < 8; jj++) h2p[jj] = sb2p[jj];
#pragma unroll
        for (int a = 0; a < NH1; a++) {
            u64 xd = pack2(h1[a], h1[a]);
            const u64* wrow = (const u64*)(sW2 + a*NH2 + 16*ph);
#pragma unroll
            for (int jj = 0; jj < 8; jj++) h2p[jj] = fma2(xd, wrow[jj], h2p[jj]);
        }
#pragma unroll
        for (int jj = 0; jj < 8; jj++) {
            float2 v = unpack2(h2p[jj]);
            v.x = fmaxf(v.x, 0.0f); v.y = fmaxf(v.y, 0.0f);
            u32 hi, lo; split_pair(v.x, v.y, hi, lo);
            int jp = 8*ph + jj;                // pair (j=2jp, 2jp+1)
            sHh[jp*PPAD + row] = hi;
            sHl[jp*PPAD + row] = lo;
        }
    }

    __syncthreads();

    // ========== GEMMs: warp = (ng, ch): 2 m-tiles x 4 nt ==========
    float c1[2][4][4], c2[2][4][4];
#pragma unroll
    for (int m = 0; m < 2; m++)
#pragma unroll
        for (int nl = 0; nl < 4; nl++)
#pragma unroll
            for (int r = 0; r < 4; r++) { c1[m][nl][r] = 0.0f; c2[m][nl][r] = 0.0f; }

    const int rbase = 32*ng + gid;     // m-tile m adds 16m

    // GEMM1: C1 = X @ W (K=64), tf32 m16n8k8 over 8 chunks (pairs of 2)
#pragma unroll
    for (int cp = 0; cp < 4; cp++) {
        // A frags for chunks 2cp, 2cp+1, both m-tiles
        uint4 a[2][2];
#pragma unroll
        for (int ck = 0; ck < 2; ck++) {
            const int k0 = (2*cp + ck)*8;
#pragma unroll
            for (int m = 0; m < 2; m++) {
                const int r = rbase + 16*m;
                a[ck][m].x = sXt[(k0 + tig)*XPAD + r];
                a[ck][m].y = sXt[(k0 + tig)*XPAD + r + 8];
                a[ck][m].z = sXt[(k0 + tig + 4)*XPAD + r];
                a[ck][m].w = sXt[(k0 + tig + 4)*XPAD + r + 8];
            }
        }
#pragma unroll
        for (int nl = 0; nl < 4; nl++) {
            uint4 bb = __ldg(&g_bt[((4*ch + nl)*4 + cp)*32 + lane]);
#pragma unroll
            for (int m = 0; m < 2; m++) {
                MMATF32(c1[m][nl], a[0][m], bb.x, bb.y);
                MMATF32(c1[m][nl], a[1][m], bb.z, bb.w);
            }
        }
    }
    // GEMM2: C2 = H @ W3 (K=32), bf16 3-product (unchanged)
#pragma unroll
    for (int s = 0; s < 2; s++) {
        const int kp = 8*s + tig;
        uint4 ah[2], al[2];
#pragma unroll
        for (int m = 0; m < 2; m++) {
            const int r = rbase + 16*m;
            ah[m].x = sHh[kp*PPAD + r];       al[m].x = sHl[kp*PPAD + r];
            ah[m].y = sHh[kp*PPAD + r + 8];   al[m].y = sHl[kp*PPAD + r + 8];
            ah[m].z = sHh[(kp+4)*PPAD + r];   al[m].z = sHl[(kp+4)*PPAD + r];
            ah[m].w = sHh[(kp+4)*PPAD + r + 8]; al[m].w = sHl[(kp+4)*PPAD + r + 8];
        }
#pragma unroll
        for (int nl = 0; nl < 4; nl++) {
            uint4 bb = __ldg(&g_b2f[((4*ch + nl)*2 + s)*32 + lane]);
            uint2 bh = make_uint2(bb.x, bb.y);
            uint2 bl = make_uint2(bb.z, bb.w);
#pragma unroll
            for (int m = 0; m < 2; m++) {
                MMA16816(c2[m][nl], ah[m], bh);
                MMA16816(c2[m][nl], ah[m], bl);
                MMA16816(c2[m][nl], al[m], bh);
            }
        }
    }

    // ========== combine: out[n,o] = sum_rows C1 * (C2 + b3) ==========
    {
#pragma unroll
        for (int m = 0; m < 2; m++) {
            const int n_loc = 2*ng + m;
#pragma unroll
            for (int nl = 0; nl < 4; nl++) {
                const int nt = 4*ch + nl;
                float b3e = sb3[8*nt + 2*tig];
                float b3o = sb3[8*nt + 2*tig + 1];
                float s0 = c1[m][nl][0]*(c2[m][nl][0] + b3e) + c1[m][nl][2]*(c2[m][nl][2] + b3e);
                float s1 = c1[m][nl][1]*(c2[m][nl][1] + b3o) + c1[m][nl][3]*(c2[m][nl][3] + b3o);
#pragma unroll
                for (int msk = 4; msk <= 16; msk <<= 1) {
                    s0 += __shfl_xor_sync(0xffffffffu, s0, msk);
                    s1 += __shfl_xor_sync(0xffffffffu, s1, msk);
                }
                if (lane < 4) {
                    sOut[n_loc*NO + 8*nt + 2*tig]     = s0;
                    sOut[n_loc*NO + 8*nt + 2*tig + 1] = s1;
                }
            }
        }
    }

    __syncthreads();

    // ========== epilogue: out (B, O, N) + bias ==========
    if (tid < 128) {
        int o = tid >> 1, half = tid & 1;
        float4 rr;
        rr.x = sOut[(half*4+0)*NO + o] + sBias[o];
        rr.y = sOut[(half*4+1)*NO + o] + sBias[o];
        rr.z = sOut[(half*4+2)*NO + o] + sBias[o];
        rr.w = sOut[(half*4+3)*NO + o] + sBias[o];
        *(float4*)(out + ((size_t)b*NO + o)*NN + n0 + half*4) = rr;
    }

    // ---- support_points passthrough ----
    if (copy_sp) {
        for (int idx = blk*NTHREADS + tid; idx < SPN; idx += gridDim.x*NTHREADS)
            out[BON + idx] = support[idx];
    }
}

extern "C" void kernel_launch(void* const* d_in, const int* in_sizes, int n_in,
                              void* d_out, int out_size) {
    const float* input   = (const float*)d_in[0];
    const float* points  = (const float*)d_in[1];
    const float* support = (const float*)d_in[2];
    const float* weight  = (const float*)d_in[3];
    const float* bias    = (const float*)d_in[4];
    const float* W1      = (const float*)d_in[5];
    const float* b1      = (const float*)d_in[6];
    const float* W2      = (const float*)d_in[7];
    const float* b2      = (const float*)d_in[8];
    const float* W3      = (const float*)d_in[9];
    const float* b3      = (const float*)d_in[10];

    static int inited = 0;
    if (!inited) {
        cudaFuncSetAttribute(pccn_kernel,
                             cudaFuncAttributeMaxDynamicSharedMemorySize,
                             SMEM_BYTES);
        inited = 1;
    }
    int copy_sp = (out_size > BON) ? 1 : 0;
    pccn_prep<<<1, NTHREADS>>>(weight, W3);
    pccn_kernel<<<NB*(NN/TN), NTHREADS, SMEM_BYTES>>>(
        input, points, support, bias, W1, b1, W2, b2, b3,
        (float*)d_out, copy_sp);
}